// round 2
// baseline (speedup 1.0000x reference)
#include <cuda_runtime.h>
#include <math.h>

typedef unsigned long long u64;

// Scratch: feat1, outs1, feat2, outs2, feat3, outs3, gates (all fp32)
__device__ float g_scratch[47448064];

__device__ __forceinline__ float sigf(float x) { return 1.f / (1.f + __expf(-x)); }
__device__ __forceinline__ float ftanh(float x) {
    float e = __expf(2.f * x);
    return 1.f - 2.f / (e + 1.f);
}

__device__ __forceinline__ void fma2(u64& d, u64 a, u64 b) {
    asm("fma.rn.f32x2 %0, %1, %2, %0;" : "+l"(d) : "l"(a), "l"(b));
}
__device__ __forceinline__ u64 ldp(const float* p) { return *(const u64*)p; }
__device__ __forceinline__ u64 midp(u64 a, u64 b) { return (a >> 32) | (b << 32); }
__device__ __forceinline__ float lo2(u64 v) { return __uint_as_float((unsigned)v); }
__device__ __forceinline__ float hi2(u64 v) { return __uint_as_float((unsigned)(v >> 32)); }

// ---------------------------------------------------------------------------
// f32x2 GRU conv. PW = out cols per thread (2 or 4). Block (8,8)=64 threads.
// Tile: 16 rows x 8*PW cols, 8 output channels per block.
// grid: (B * Cout/8, H/16, W/(8*PW))
// mode 0: gates (sigmoid, out=gates buf). mode 1: cand (+GRU update, out=h).
// ---------------------------------------------------------------------------
template<int PW>
__global__ __launch_bounds__(64)
void gru_conv2(const float* __restrict__ xt, const float* __restrict__ hprev,
               const float* __restrict__ Wt, const float* __restrict__ bias,
               const float* __restrict__ gatesIn, float* __restrict__ out,
               int Cx, int Ch, int Cout, int H, int W, int mode)
{
    constexpr int TW = 8 * PW;     // tile width
    constexpr int SW = TW + 4;     // smem row stride (even)
    constexpr int LW = TW + 2;     // loaded width (halo)
    const int cgrp = Cout >> 3;
    int b   = blockIdx.x / cgrp;
    int co0 = (blockIdx.x % cgrp) * 8;
    int oy0 = blockIdx.y * 16;
    int ox0 = blockIdx.z * TW;
    int tx = threadIdx.x, ty = threadIdx.y;
    int tid = ty * 8 + tx;

    __shared__ float tile[8][18][SW];
    __shared__ u64 wdup[8][8][9];

    int CinTot = Cx + Ch;
    int CinEff = hprev ? CinTot : Cx;   // h0 == 0 -> skip h channels at t=0
    int HW = H * W;

    u64 acc[2][PW / 2][8];
#pragma unroll
    for (int r = 0; r < 2; r++)
#pragma unroll
        for (int p = 0; p < PW / 2; p++)
#pragma unroll
            for (int co = 0; co < 8; co++) acc[r][p][co] = 0ULL;

    for (int ci0 = 0; ci0 < CinEff; ci0 += 8) {
        bool isH = (ci0 >= Cx);
        int cbase = isH ? (ci0 - Cx) : ci0;
        const float* sp = (isH ? hprev : xt) + ((size_t)b * (isH ? Ch : Cx) + cbase) * HW;
        const float* rp = (isH && mode) ? gatesIn + ((size_t)b * 2 * Ch + cbase) * HW : nullptr;

        __syncthreads();
        // input tile: 8 channels x 18 x LW, zero-padded halo
        if (rp) {
            for (int i = tid; i < 8 * 18 * LW; i += 64) {
                int c = i / (18 * LW);
                int rrem = i - c * (18 * LW);
                int ly = rrem / LW;
                int lx = rrem - ly * LW;
                int gy = oy0 - 1 + ly, gx = ox0 - 1 + lx;
                float v = 0.f;
                if ((unsigned)gy < (unsigned)H && (unsigned)gx < (unsigned)W) {
                    int o = c * HW + gy * W + gx;
                    v = sp[o] * rp[o];           // r * h
                }
                tile[c][ly][lx] = v;
            }
        } else {
            for (int i = tid; i < 8 * 18 * LW; i += 64) {
                int c = i / (18 * LW);
                int rrem = i - c * (18 * LW);
                int ly = rrem / LW;
                int lx = rrem - ly * LW;
                int gy = oy0 - 1 + ly, gx = ox0 - 1 + lx;
                float v = 0.f;
                if ((unsigned)gy < (unsigned)H && (unsigned)gx < (unsigned)W)
                    v = sp[c * HW + gy * W + gx];
                tile[c][ly][lx] = v;
            }
        }
        // weights: 64 threads = 8c x 8co, duplicate into f32x2
        {
            int c = tid >> 3, co = tid & 7;
            const float* w = Wt + ((size_t)(co0 + co) * CinTot + (ci0 + c)) * 9;
#pragma unroll
            for (int k = 0; k < 9; k++) {
                unsigned bitsv = __float_as_uint(w[k]);
                wdup[c][co][k] = (u64)bitsv | ((u64)bitsv << 32);
            }
        }
        __syncthreads();

#pragma unroll
        for (int c = 0; c < 8; c++) {
            u64 P[4][PW + 1];
#pragma unroll
            for (int k = 0; k < 4; k++) {
                const float* rw = &tile[c][2 * ty + k][PW * tx];
                u64 A = ldp(rw), Bq = ldp(rw + 2);
                P[k][0] = A; P[k][1] = midp(A, Bq); P[k][2] = Bq;
                if (PW == 4) {
                    u64 Cq = ldp(rw + 4);
                    P[k][3] = midp(Bq, Cq); P[k][4] = Cq;
                }
            }
#pragma unroll
            for (int co = 0; co < 8; co++) {
#pragma unroll
                for (int i = 0; i < 3; i++) {
#pragma unroll
                    for (int j = 0; j < 3; j++) {
                        u64 w = wdup[c][co][i * 3 + j];
#pragma unroll
                        for (int p = 0; p < PW / 2; p++) {
                            fma2(acc[0][p][co], P[i][j + 2 * p], w);
                            fma2(acc[1][p][co], P[i + 1][j + 2 * p], w);
                        }
                    }
                }
            }
        }
    }

    int oy = oy0 + 2 * ty;
    int ox = ox0 + PW * tx;
    if (mode == 0) {
#pragma unroll
        for (int co = 0; co < 8; co++) {
            float bz = bias[co0 + co];
            float* op = out + (((size_t)b * Cout + co0 + co) * H + oy) * W + ox;
#pragma unroll
            for (int r = 0; r < 2; r++) {
#pragma unroll
                for (int p = 0; p < PW / 2; p++) {
                    u64 v = acc[r][p][co];
                    float2 f;
                    f.x = sigf(lo2(v) + bz);
                    f.y = sigf(hi2(v) + bz);
                    *(float2*)(op + r * W + 2 * p) = f;
                }
            }
        }
    } else {
#pragma unroll
        for (int co = 0; co < 8; co++) {
            int cc = co0 + co;
            float bz = bias[cc];
            const float* zp = gatesIn + (((size_t)b * 2 * Ch + Ch + cc) * H + oy) * W + ox;
            const float* hp2 = hprev ? hprev + (((size_t)b * Ch + cc) * H + oy) * W + ox : nullptr;
            float* op = out + (((size_t)b * Ch + cc) * H + oy) * W + ox;
#pragma unroll
            for (int r = 0; r < 2; r++) {
#pragma unroll
                for (int p = 0; p < PW / 2; p++) {
                    u64 v = acc[r][p][co];
                    float z0 = zp[r * W + 2 * p], z1 = zp[r * W + 2 * p + 1];
                    float h0 = 0.f, h1 = 0.f;
                    if (hp2) { h0 = hp2[r * W + 2 * p]; h1 = hp2[r * W + 2 * p + 1]; }
                    float2 f;
                    f.x = z0 * h0 + (1.f - z0) * ftanh(lo2(v) + bz);
                    f.y = z1 * h1 + (1.f - z1) * ftanh(hi2(v) + bz);
                    *(float2*)(op + r * W + 2 * p) = f;
                }
            }
        }
    }
}

// ---------------------------------------------------------------------------
// Stride-2 3x3 conv (pad 1) + leaky relu(0.2), over all N = T*B samples.
// ---------------------------------------------------------------------------
#define CSTEP2 4
__global__ void conv_s2_lrelu(const float* __restrict__ in, const float* __restrict__ Wt,
                              const float* __restrict__ bias, float* __restrict__ out,
                              int Cin, int Cout, int Hin, int Win, int sOuter, int sInner)
{
    int coutBlocks = Cout >> 3;
    int n  = blockIdx.x / coutBlocks;
    int cb = blockIdx.x % coutBlocks;
    int co0 = cb * 8;
    int t = n / 8, b = n % 8;
    const float* inN = in + (size_t)t * sOuter + (size_t)b * sInner;
    int Hout = Hin >> 1, Wout = Win >> 1;
    int oy0 = blockIdx.y * 16, ox0 = blockIdx.z * 16;
    int tx = threadIdx.x, ty = threadIdx.y;
    int tid = ty * 16 + tx;

    __shared__ float tile[CSTEP2][33][35];
    __shared__ float ws[CSTEP2][8][9];

    float acc0[8], acc1[8];
#pragma unroll
    for (int i = 0; i < 8; i++) { acc0[i] = 0.f; acc1[i] = 0.f; }

    for (int ci0 = 0; ci0 < Cin; ci0 += CSTEP2) {
        __syncthreads();
        for (int i = tid; i < CSTEP2 * 1089; i += 128) {
            int c = i / 1089, p = i % 1089;
            int ly = p / 33, lx = p % 33;
            int gy = 2 * oy0 - 1 + ly, gx = 2 * ox0 - 1 + lx;
            float v = 0.f;
            int ci = ci0 + c;
            if (ci < Cin && gy >= 0 && gy < Hin && gx >= 0 && gx < Win)
                v = inN[((size_t)ci * Hin + gy) * Win + gx];
            tile[c][ly][lx] = v;
        }
        for (int i = tid; i < CSTEP2 * 72; i += 128) {
            int c = i / 72, r = i % 72;
            int co = r / 9, k = r % 9;
            float wv = 0.f;
            if (ci0 + c < Cin)
                wv = Wt[((size_t)(co0 + co) * Cin + (ci0 + c)) * 9 + k];
            ws[c][co][k] = wv;
        }
        __syncthreads();

#pragma unroll
        for (int c = 0; c < CSTEP2; c++) {
            float a[5][3];
#pragma unroll
            for (int i = 0; i < 5; i++)
#pragma unroll
                for (int j = 0; j < 3; j++)
                    a[i][j] = tile[c][4 * ty + i][2 * tx + j];
#pragma unroll
            for (int co = 0; co < 8; co++) {
                float w0 = ws[c][co][0], w1 = ws[c][co][1], w2 = ws[c][co][2];
                float w3 = ws[c][co][3], w4 = ws[c][co][4], w5 = ws[c][co][5];
                float w6 = ws[c][co][6], w7 = ws[c][co][7], w8 = ws[c][co][8];
                acc0[co] += a[0][0]*w0 + a[0][1]*w1 + a[0][2]*w2
                          + a[1][0]*w3 + a[1][1]*w4 + a[1][2]*w5
                          + a[2][0]*w6 + a[2][1]*w7 + a[2][2]*w8;
                acc1[co] += a[2][0]*w0 + a[2][1]*w1 + a[2][2]*w2
                          + a[3][0]*w3 + a[3][1]*w4 + a[3][2]*w5
                          + a[4][0]*w6 + a[4][1]*w7 + a[4][2]*w8;
            }
        }
    }

    int oy = oy0 + 2 * ty, ox = ox0 + tx;
#pragma unroll
    for (int co = 0; co < 8; co++) {
        float bz = bias[co0 + co];
        float v0 = acc0[co] + bz, v1 = acc1[co] + bz;
        v0 = v0 > 0.f ? v0 : 0.2f * v0;
        v1 = v1 > 0.f ? v1 : 0.2f * v1;
        size_t o = (((size_t)n * Cout + co0 + co) * Hout + oy) * Wout + ox;
        out[o]        = v0;
        out[o + Wout] = v1;
    }
}

extern "C" void kernel_launch(void* const* d_in, const int* in_sizes, int n_in,
                              void* d_out, int out_size)
{
    const float* x   = (const float*)d_in[0];
    const float* W1  = (const float*)d_in[1];
    const float* b1  = (const float*)d_in[2];
    const float* Wg1 = (const float*)d_in[3];
    const float* bg1 = (const float*)d_in[4];
    const float* Wc1 = (const float*)d_in[5];
    const float* bc1 = (const float*)d_in[6];
    const float* W2  = (const float*)d_in[7];
    const float* b2  = (const float*)d_in[8];
    const float* Wg2 = (const float*)d_in[9];
    const float* bg2 = (const float*)d_in[10];
    const float* Wc2 = (const float*)d_in[11];
    const float* bc2 = (const float*)d_in[12];
    const float* W3  = (const float*)d_in[13];
    const float* b3  = (const float*)d_in[14];
    const float* Wg3 = (const float*)d_in[15];
    const float* bg3 = (const float*)d_in[16];
    const float* Wc3 = (const float*)d_in[17];
    const float* bc3 = (const float*)d_in[18];

    float* base = nullptr;
    cudaGetSymbolAddress((void**)&base, g_scratch);

    float* feat1 = base;                 // 10*8*16*64*64  = 5242880
    float* outs1 = base + 5242880;       // 10*8*64*64*64  = 20971520
    float* feat2 = base + 26214400;      // 10*8*64*32*32  = 5242880
    float* outs2 = base + 31457280;      // 10*8*96*32*32  = 7864320
    float* feat3 = base + 39321600;      // 10*8*96*16*16  = 1966080
    float* outs3 = base + 41287680;      // 10*8*96*16*16  = 1966080
    float* gates = base + 43253760;      // max 8*128*64*64 = 4194304

    dim3 blkc(16, 8);
    dim3 blkg(8, 8);

    // ---------------- Stage 1 (H=W=64, Cx=16, Ch=64) ----------------
    conv_s2_lrelu<<<dim3(80 * 2, 4, 4), blkc>>>(x, W1, b1, feat1,
                                                1, 16, 128, 128, 16384, 163840);
    for (int t = 0; t < 10; t++) {
        const float* xt = feat1 + (size_t)t * 8 * 16 * 64 * 64;
        const float* hp = t ? outs1 + (size_t)(t - 1) * 8 * 64 * 64 * 64 : nullptr;
        float* hn = outs1 + (size_t)t * 8 * 64 * 64 * 64;
        gru_conv2<4><<<dim3(8 * 16, 4, 2), blkg>>>(xt, hp, Wg1, bg1, gates, gates,
                                                   16, 64, 128, 64, 64, 0);
        gru_conv2<4><<<dim3(8 * 8, 4, 2), blkg>>>(xt, hp, Wc1, bc1, gates, hn,
                                                  16, 64, 64, 64, 64, 1);
    }

    // ---------------- Stage 2 (H=W=32, Cx=64, Ch=96) ----------------
    conv_s2_lrelu<<<dim3(80 * 8, 2, 2), blkc>>>(outs1, W2, b2, feat2,
                                                64, 64, 64, 64, 8 * 64 * 4096, 64 * 4096);
    for (int t = 0; t < 10; t++) {
        const float* xt = feat2 + (size_t)t * 8 * 64 * 32 * 32;
        const float* hp = t ? outs2 + (size_t)(t - 1) * 8 * 96 * 32 * 32 : nullptr;
        float* hn = outs2 + (size_t)t * 8 * 96 * 32 * 32;
        gru_conv2<4><<<dim3(8 * 24, 2, 1), blkg>>>(xt, hp, Wg2, bg2, gates, gates,
                                                   64, 96, 192, 32, 32, 0);
        gru_conv2<4><<<dim3(8 * 12, 2, 1), blkg>>>(xt, hp, Wc2, bc2, gates, hn,
                                                   64, 96, 96, 32, 32, 1);
    }

    // ---------------- Stage 3 (H=W=16, Cx=96, Ch=96) ----------------
    conv_s2_lrelu<<<dim3(80 * 12, 1, 1), blkc>>>(outs2, W3, b3, feat3,
                                                 96, 96, 32, 32, 8 * 96 * 1024, 96 * 1024);
    for (int t = 0; t < 10; t++) {
        const float* xt = feat3 + (size_t)t * 8 * 96 * 16 * 16;
        const float* hp = t ? outs3 + (size_t)(t - 1) * 8 * 96 * 16 * 16 : nullptr;
        float* hn = outs3 + (size_t)t * 8 * 96 * 16 * 16;
        gru_conv2<2><<<dim3(8 * 24, 1, 1), blkg>>>(xt, hp, Wg3, bg3, gates, gates,
                                                   96, 96, 192, 16, 16, 0);
        gru_conv2<2><<<dim3(8 * 12, 1, 1), blkg>>>(xt, hp, Wc3, bc3, gates, hn,
                                                   96, 96, 96, 16, 16, 1);
    }

    // ---------------- Assemble output: (h1, h2, h3) flattened ----------------
    float* out = (float*)d_out;
    cudaMemcpyAsync(out,
                    outs1 + 9UL * 8 * 64 * 4096,
                    (size_t)8 * 64 * 4096 * sizeof(float),
                    cudaMemcpyDeviceToDevice, 0);
    cudaMemcpyAsync(out + 2097152,
                    outs2 + 9UL * 8 * 96 * 1024,
                    (size_t)8 * 96 * 1024 * sizeof(float),
                    cudaMemcpyDeviceToDevice, 0);
    cudaMemcpyAsync(out + 2097152 + 786432,
                    outs3 + 9UL * 8 * 96 * 256,
                    (size_t)8 * 96 * 256 * sizeof(float),
                    cudaMemcpyDeviceToDevice, 0);
}